// round 6
// baseline (speedup 1.0000x reference)
#include <cuda_runtime.h>

#define ROWS  144
#define NCOLS 576
#define DEG   6
#define ITER  3
#define TPB   576   // 4 threads per row, 144 rows, 1 batch element per block

// Sparse structure of H: column indices of the 6 ones per row.
__device__ int   g_cols[ROWS * DEG];
// Per-iteration quantizer constants:
// [0]=lam (=2*c*delta), [1..4]=k_i=exp(-c*q_i^2), [5..8]=k_i*q_i,
// [9]=qz0=quantize(0), [10]=144*qz0
__device__ float g_q[ITER][11];

// One block per row, 576 threads: coalesced read + ballot-based ordered rank.
// Block 0 / thread 0 additionally precomputes the quantizer constants.
__global__ void prep_kernel(const float* __restrict__ H,
                            const float* __restrict__ eta,
                            const float* __restrict__ qk)
{
    __shared__ int wcnt[18];
    __shared__ int wpre[18];
    const int row  = blockIdx.x;
    const int j    = threadIdx.x;          // 0..575
    const int w    = j >> 5, lane = j & 31;
    const float v  = H[row * NCOLS + j];
    const unsigned mask = __ballot_sync(0xffffffffu, v != 0.0f);
    if (lane == 0) wcnt[w] = __popc(mask);
    __syncthreads();
    if (j == 0) {
        int s = 0;
        #pragma unroll
        for (int k = 0; k < 18; ++k) { wpre[k] = s; s += wcnt[k]; }
    }
    __syncthreads();
    if (v != 0.0f) {
        int rank = wpre[w] + __popc(mask & ((1u << lane) - 1u));
        if (rank < DEG) g_cols[row * DEG + rank] = j;
    }

    if (row == 0 && j == 0) {
        const float q0 = qk[0], q1 = qk[1], q2 = qk[2], q3 = qk[3];
        const float dq = (q3 - q0) * (1.0f / 3.0f);
        #pragma unroll
        for (int t = 0; t < ITER; ++t) {
            float et  = eta[t];
            float c   = 1.0f / (2.0f * et * et + 1e-12f);
            float lam = 2.0f * c * dq;
            float k0 = __expf(-c * q0 * q0), k1 = __expf(-c * q1 * q1);
            float k2 = __expf(-c * q2 * q2), k3 = __expf(-c * q3 * q3);
            g_q[t][0] = lam;
            g_q[t][1] = k0; g_q[t][2] = k1; g_q[t][3] = k2; g_q[t][4] = k3;
            g_q[t][5] = k0 * q0; g_q[t][6] = k1 * q1;
            g_q[t][7] = k2 * q2; g_q[t][8] = k3 * q3;
            float den = (k0 + k1) + (k2 + k3);
            float num = (k0 * q0 + k1 * q1) + (k2 * q2 + k3 * q3);
            float qz0 = num / den;
            g_q[t][9]  = qz0;
            g_q[t][10] = (float)ROWS * qz0;
        }
    }
}

__global__ __launch_bounds__(TPB, 3) void decode_kernel(
    const float* __restrict__ r,
    const float* __restrict__ alpha,
    const float* __restrict__ beta,
    float* __restrict__ out)
{
    __shared__ float sr[NCOLS];         // r for this batch element
    __shared__ float sc[2][NCOLS];      // double-buffered column sums

    const int tid = threadIdx.x;
    const int b   = blockIdx.x;
    const int row = tid >> 2;           // 0..143
    const int q   = tid & 3;            // quarter of the row
    // Edge split 2/2/1/1: threads 0,1 take 2 edges; threads 2,3 take 1.
    const int ne  = (q < 2) ? 2 : 1;
    const int e0  = (q < 2) ? (q * 2) : (q + 2);  // first global edge index

    sr[tid] = r[(size_t)b * NCOLS + tid];

    int   ci[2];
    float M[2], E[2], S[2];
    #pragma unroll
    for (int k = 0; k < 2; ++k)
        ci[k] = g_cols[row * DEG + e0 + ((k < ne) ? k : 0)];
    __syncthreads();
    #pragma unroll
    for (int k = 0; k < 2; ++k) M[k] = sr[ci[k]];   // M = H*r at support

    #pragma unroll
    for (int t = 0; t < ITER; ++t) {
        const float lam = g_q[t][0];
        const float k0 = g_q[t][1], k1 = g_q[t][2];
        const float k2 = g_q[t][3], k3 = g_q[t][4];
        const float kq0 = g_q[t][5], kq1 = g_q[t][6];
        const float kq2 = g_q[t][7], kq3 = g_q[t][8];
        const float qz0  = g_q[t][9];
        const float init = g_q[t][10];
        const float a  = alpha[t];
        const float bt = beta[t];

        // Soft quantization via geometric weights:
        //   w_i ∝ k_i * u^i, u = exp(2*c*dq*x). Overflow-safe: factor out the
        //   largest power (sign-dependent), using v = exp(-lam*|x|) <= 1.
        auto quant = [&](float x) -> float {
            float v  = __expf(-lam * fabsf(x));
            float v2 = v * v;
            float v3 = v2 * v;
            bool  p  = (x >= 0.0f);
            float a0 = p ? v3 : 1.0f;
            float a1 = p ? v2 : v;
            float a2 = p ? v  : v2;
            float a3 = p ? 1.0f : v3;
            float den = fmaf(a0, k0,  fmaf(a1, k1,  fmaf(a2, k2,  a3 * k3)));
            float num = fmaf(a0, kq0, fmaf(a1, kq1, fmaf(a2, kq2, a3 * kq3)));
            return __fdividef(num, den);
        };

        // Init column sums: sum_E[j] = 144*qz0 + sum_{support}(E - qz0)
        float* cs = sc[t & 1];
        cs[tid] = init;

        // Row stats over this thread's edges
        float m1 = 3.0e38f, m2 = 3.0e38f, sp = 1.0f;
        int   id = 7;
        #pragma unroll
        for (int k = 0; k < 2; ++k) {
            if (k < ne) {
                float m_ = M[k];
                float am = fabsf(m_);
                float sg = (m_ > 0.0f) ? 1.0f : ((m_ < 0.0f) ? -1.0f : 0.0f);
                S[k] = sg;
                sp  *= sg;
                int gk = e0 + k;
                if (am < m1)      { m2 = m1; m1 = am; id = gk; }
                else if (am < m2) { m2 = am; }
            }
        }
        // Butterfly merge across the 4 lanes of this row (intra-warp).
        #pragma unroll
        for (int d = 1; d <= 2; d <<= 1) {
            float om1 = __shfl_xor_sync(0xffffffffu, m1, d);
            float om2 = __shfl_xor_sync(0xffffffffu, m2, d);
            int   oid = __shfl_xor_sync(0xffffffffu, id, d);
            float osp = __shfl_xor_sync(0xffffffffu, sp, d);
            sp *= osp;
            if (om1 < m1 || (om1 == m1 && oid < id)) {
                m2 = fminf(m1, om2); m1 = om1; id = oid;
            } else {
                m2 = fminf(m2, om1);
            }
        }

        const float asp = a * sp;
        #pragma unroll
        for (int k = 0; k < 2; ++k) {
            int gk = e0 + k;
            float eab = (gk == id) ? m2 : m1;
            E[k] = quant(asp * S[k] * fmaxf(0.0f, eab - bt));
        }
        __syncthreads();   // cs init visible; prior-iter cs readers done
        #pragma unroll
        for (int k = 0; k < 2; ++k)
            if (k < ne) atomicAdd(&cs[ci[k]], E[k] - qz0);
        __syncthreads();   // column sums complete
        if (t + 1 < ITER) {
            #pragma unroll
            for (int k = 0; k < 2; ++k)
                M[k] = quant(sr[ci[k]] + cs[ci[k]] - E[k]);
        }
    }

    const float* csf = sc[(ITER - 1) & 1];
    out[(size_t)b * NCOLS + tid] = sr[tid] + csf[tid];
}

extern "C" void kernel_launch(void* const* d_in, const int* in_sizes, int n_in,
                              void* d_out, int out_size)
{
    const float* r     = (const float*)d_in[0];
    const float* H     = (const float*)d_in[1];
    const float* alpha = (const float*)d_in[2];
    const float* beta  = (const float*)d_in[3];
    const float* eta   = (const float*)d_in[4];
    const float* qk    = (const float*)d_in[5];
    float* out = (float*)d_out;

    const int batch = in_sizes[0] / NCOLS;   // 512

    prep_kernel<<<ROWS, NCOLS>>>(H, eta, qk);
    decode_kernel<<<batch, TPB>>>(r, alpha, beta, out);
}

// round 7
// speedup vs baseline: 1.1335x; 1.1335x over previous
#include <cuda_runtime.h>

#define ROWS  144
#define NCOLS 576
#define DEG   6
#define ITER  3
#define TPB   288   // 2 threads per row; each thread also owns 2 columns
#define PAD   12    // slots per column in the scatter buffer (max col degree)

// Sparse structure of H.
__device__ int   g_cols[ROWS * DEG];      // column index of each edge
__device__ int   g_eslot[ROWS * DEG];     // col*PAD + slot for each edge
__device__ int   g_coldeg[NCOLS];         // column degrees
// Per-iteration quantizer constants:
// [0]=lam, [1..4]=k_i, [5..8]=k_i*q_i, [9]=qz0
__device__ float g_q[ITER][10];

__global__ void zero_kernel() {
    g_coldeg[threadIdx.x] = 0;
}

// One block per row, 576 threads: coalesced read + ballot-based ordered rank.
// Block 0 / thread 0 additionally precomputes the quantizer constants.
__global__ void prep_kernel(const float* __restrict__ H,
                            const float* __restrict__ eta,
                            const float* __restrict__ qk)
{
    __shared__ int wcnt[18];
    __shared__ int wpre[18];
    const int row  = blockIdx.x;
    const int j    = threadIdx.x;          // 0..575
    const int w    = j >> 5, lane = j & 31;
    const float v  = H[row * NCOLS + j];
    const unsigned mask = __ballot_sync(0xffffffffu, v != 0.0f);
    if (lane == 0) wcnt[w] = __popc(mask);
    __syncthreads();
    if (j == 0) {
        int s = 0;
        #pragma unroll
        for (int k = 0; k < 18; ++k) { wpre[k] = s; s += wcnt[k]; }
    }
    __syncthreads();
    if (v != 0.0f) {
        int rank = wpre[w] + __popc(mask & ((1u << lane) - 1u));
        if (rank < DEG) {
            g_cols[row * DEG + rank] = j;
            int slot = atomicAdd(&g_coldeg[j], 1);   // private slot in column j
            g_eslot[row * DEG + rank] = j * PAD + slot;
        }
    }

    if (row == 0 && j == 0) {
        const float q0 = qk[0], q1 = qk[1], q2 = qk[2], q3 = qk[3];
        const float dq = (q3 - q0) * (1.0f / 3.0f);
        #pragma unroll
        for (int t = 0; t < ITER; ++t) {
            float et  = eta[t];
            float c   = 1.0f / (2.0f * et * et + 1e-12f);
            float lam = 2.0f * c * dq;
            float k0 = __expf(-c * q0 * q0), k1 = __expf(-c * q1 * q1);
            float k2 = __expf(-c * q2 * q2), k3 = __expf(-c * q3 * q3);
            g_q[t][0] = lam;
            g_q[t][1] = k0; g_q[t][2] = k1; g_q[t][3] = k2; g_q[t][4] = k3;
            g_q[t][5] = k0 * q0; g_q[t][6] = k1 * q1;
            g_q[t][7] = k2 * q2; g_q[t][8] = k3 * q3;
            float den = (k0 + k1) + (k2 + k3);
            float num = (k0 * q0 + k1 * q1) + (k2 * q2 + k3 * q3);
            g_q[t][9] = num / den;   // quantize(0)
        }
    }
}

__global__ __launch_bounds__(TPB) void decode_kernel(
    const float* __restrict__ r,
    const float* __restrict__ alpha,
    const float* __restrict__ beta,
    float* __restrict__ out)
{
    __shared__ float sr[NCOLS];          // r for this batch element
    __shared__ float cs[NCOLS];          // column sums
    __shared__ float sE[NCOLS * PAD];    // slotted E scatter buffer

    const int tid  = threadIdx.x;
    const int b    = blockIdx.x;
    const int row  = tid >> 1;           // 0..143
    const int half = tid & 1;            // which 3 edges of the row

    // Vectorized load of r (288 float2 = 576 floats)
    ((float2*)sr)[tid] = ((const float2*)(r + (size_t)b * NCOLS))[tid];

    // Row role: 3 edges.
    int   ci[3], so[3];
    float M[3], E[3], S[3];
    #pragma unroll
    for (int k = 0; k < 3; ++k) {
        ci[k] = g_cols [row * DEG + half * 3 + k];
        so[k] = g_eslot[row * DEG + half * 3 + k];
    }
    // Column role: 2 columns per thread (coalesced with output).
    const int j0 = tid, j1 = tid + TPB;
    const float fdeg0 = (float)(ROWS - g_coldeg[j0]);
    const float fdeg1 = (float)(ROWS - g_coldeg[j1]);
    const int  deg0  = ROWS - (int)fdeg0;
    const int  deg1  = ROWS - (int)fdeg1;

    __syncthreads();
    #pragma unroll
    for (int k = 0; k < 3; ++k) M[k] = sr[ci[k]];   // M = H*r at support

    #pragma unroll
    for (int t = 0; t < ITER; ++t) {
        const float lam = g_q[t][0];
        const float k0 = g_q[t][1], k1 = g_q[t][2];
        const float k2 = g_q[t][3], k3 = g_q[t][4];
        const float kq0 = g_q[t][5], kq1 = g_q[t][6];
        const float kq2 = g_q[t][7], kq3 = g_q[t][8];
        const float qz0 = g_q[t][9];
        const float a   = alpha[t];
        const float bt  = beta[t];

        // Soft quantization via geometric weights:
        //   w_i ∝ k_i * u^i, u = exp(2*c*dq*x). Overflow-safe: factor out the
        //   largest power (sign-dependent), using v = exp(-lam*|x|) <= 1.
        auto quant = [&](float x) -> float {
            float v  = __expf(-lam * fabsf(x));
            float v2 = v * v;
            float v3 = v2 * v;
            bool  p  = (x >= 0.0f);
            float a0 = p ? v3 : 1.0f;
            float a1 = p ? v2 : v;
            float a2 = p ? v  : v2;
            float a3 = p ? 1.0f : v3;
            float den = fmaf(a0, k0,  fmaf(a1, k1,  fmaf(a2, k2,  a3 * k3)));
            float num = fmaf(a0, kq0, fmaf(a1, kq1, fmaf(a2, kq2, a3 * kq3)));
            return __fdividef(num, den);
        };

        // ---- Row phase: stats over this thread's 3 edges + pair merge ----
        float m1 = 3.0e38f, m2 = 3.0e38f, sp = 1.0f;
        int   id = 0;
        #pragma unroll
        for (int k = 0; k < 3; ++k) {
            float m_ = M[k];
            float am = fabsf(m_);
            float sg = (m_ > 0.0f) ? 1.0f : ((m_ < 0.0f) ? -1.0f : 0.0f);
            S[k] = sg;
            sp  *= sg;
            int gk = half * 3 + k;
            if (am < m1)      { m2 = m1; m1 = am; id = gk; }
            else if (am < m2) { m2 = am; }
        }
        // Merge with partner half (pairs are intra-warp: lanes 2u, 2u+1)
        float om1 = __shfl_xor_sync(0xffffffffu, m1, 1);
        float om2 = __shfl_xor_sync(0xffffffffu, m2, 1);
        int   oid = __shfl_xor_sync(0xffffffffu, id, 1);
        float osp = __shfl_xor_sync(0xffffffffu, sp, 1);
        sp *= osp;
        if (om1 < m1 || (om1 == m1 && oid < id)) {
            m2 = fminf(m1, om2); m1 = om1; id = oid;
        } else {
            m2 = fminf(m2, om1);
        }

        const float asp = a * sp;
        #pragma unroll
        for (int k = 0; k < 3; ++k) {
            int gk = half * 3 + k;
            float eab = (gk == id) ? m2 : m1;
            E[k] = quant(asp * S[k] * fmaxf(0.0f, eab - bt));
            sE[so[k]] = E[k];              // plain STS, conflict-free slot
        }
        __syncthreads();   // scatter complete

        // ---- Column phase: gather. sum_E[j] = (144-deg_j)*qz0 + sum E ----
        float s0 = fdeg0 * qz0;
        for (int s = 0; s < deg0; ++s) s0 += sE[j0 * PAD + s];
        float s1 = fdeg1 * qz0;
        for (int s = 0; s < deg1; ++s) s1 += sE[j1 * PAD + s];

        if (t + 1 < ITER) {
            cs[j0] = s0;
            cs[j1] = s1;
            __syncthreads();   // column sums visible
            #pragma unroll
            for (int k = 0; k < 3; ++k)
                M[k] = quant(sr[ci[k]] + cs[ci[k]] - E[k]);
        } else {
            // Last iteration: output directly from registers, no cs, no sync.
            out[(size_t)b * NCOLS + j0] = sr[j0] + s0;
            out[(size_t)b * NCOLS + j1] = sr[j1] + s1;
        }
    }
}

extern "C" void kernel_launch(void* const* d_in, const int* in_sizes, int n_in,
                              void* d_out, int out_size)
{
    const float* r     = (const float*)d_in[0];
    const float* H     = (const float*)d_in[1];
    const float* alpha = (const float*)d_in[2];
    const float* beta  = (const float*)d_in[3];
    const float* eta   = (const float*)d_in[4];
    const float* qk    = (const float*)d_in[5];
    float* out = (float*)d_out;

    const int batch = in_sizes[0] / NCOLS;   // 512

    zero_kernel<<<1, NCOLS>>>();
    prep_kernel<<<ROWS, NCOLS>>>(H, eta, qk);
    decode_kernel<<<batch, TPB>>>(r, alpha, beta, out);
}